// round 13
// baseline (speedup 1.0000x reference)
#include <cuda_runtime.h>
#include <cuda_bf16.h>
#include <cuda_fp16.h>
#include <cstdint>

// ---------------------------------------------------------------------------
// EncoderSaliencySelection, GB300 sm_103a (PTX target compute_103: no tcgen05;
// tokens GEMM uses fp16 mma.sync.m16n8k16, fp32 accumulate)
// ---------------------------------------------------------------------------

#define Bq   32
#define Nq   4096
#define IDIM 125
#define ADIM 128
#define KDIM 64
#define DMOD 1024
#define HID  64
#define KEFF 256
#define EPSq 1e-6f

__device__ float g_sal [Bq * Nq];
__device__ float g_csal[Bq * Nq];
__device__ int   g_top [Bq * KEFF];
__device__ float g_cloud[Bq * KEFF * KDIM];

// packed f32x2 helpers (element-wise exact)
__device__ __forceinline__ unsigned long long pack_dup(float v) {
    unsigned long long r;
    asm("mov.b64 %0, {%1, %1};" : "=l"(r) : "f"(v));
    return r;
}
__device__ __forceinline__ unsigned long long pack2(float a, float b) {
    unsigned long long r;
    asm("mov.b64 %0, {%1, %2};" : "=l"(r) : "f"(a), "f"(b));
    return r;
}
__device__ __forceinline__ void fma2(unsigned long long& acc,
                                     unsigned long long a, unsigned long long b) {
    asm("fma.rn.f32x2 %0, %1, %2, %0;" : "+l"(acc) : "l"(a), "l"(b));
}
__device__ __forceinline__ float lo32(unsigned long long v) {
    return __uint_as_float((unsigned)(v & 0xffffffffull));
}
__device__ __forceinline__ float hi32(unsigned long long v) {
    return __uint_as_float((unsigned)(v >> 32));
}
// pack (lo, hi) floats -> half2 in one cvt
__device__ __forceinline__ uint32_t h2pack(float lo, float hi) {
    uint32_t r;
    asm("cvt.rn.f16x2.f32 %0, %1, %2;" : "=r"(r) : "f"(hi), "f"(lo));
    return r;
}

// ---------------------------------------------------------------------------
// K1: MLP scorer tiled GEMM (unchanged from R8/R10 passing version)
// ---------------------------------------------------------------------------
#define CHUNK 25
__global__ __launch_bounds__(256)
void mlp_kernel(const float* __restrict__ x,  const float* __restrict__ W1,
                const float* __restrict__ b1, const float* __restrict__ W2,
                const float* __restrict__ b2)
{
    __shared__ float pool[128 * 65];
    __shared__ float b1s[HID], W2s[HID];

    float* Xs = pool;                       // [128][28]
    float* Wc = pool + 128 * 28;            // [25][64]

    const int tid = threadIdx.x;
    if (tid < HID) { b1s[tid] = b1[tid]; W2s[tid] = W2[tid]; }

    const int p0 = blockIdx.x * 128;
    const int tx = tid & 15;
    const int ty = tid >> 4;

    unsigned long long acc[8][2];
#pragma unroll
    for (int q = 0; q < 8; q++) { acc[q][0] = 0ull; acc[q][1] = 0ull; }

    for (int cc = 0; cc < 5; cc++) {
        __syncthreads();
        for (int i = tid; i < (CHUNK * HID) / 4; i += 256)
            reinterpret_cast<float4*>(Wc)[i] =
                reinterpret_cast<const float4*>(W1 + cc * CHUNK * HID)[i];
        for (int i = tid; i < 128 * CHUNK; i += 256) {
            int p = i / CHUNK, c = i - p * CHUNK;
            Xs[p * 28 + c] = x[(size_t)(p0 + p) * IDIM + cc * CHUNK + c];
        }
        __syncthreads();

#pragma unroll
        for (int c4 = 0; c4 < 6; c4++) {
#pragma unroll
            for (int half = 0; half < 2; half++) {
                float4 xa[4];
#pragma unroll
                for (int q = 0; q < 4; q++)
                    xa[q] = *reinterpret_cast<const float4*>(
                        &Xs[(ty * 8 + half * 4 + q) * 28 + c4 * 4]);
#pragma unroll
                for (int j = 0; j < 4; j++) {
                    ulonglong2 w = *reinterpret_cast<const ulonglong2*>(
                        &Wc[(c4 * 4 + j) * HID + tx * 4]);
#pragma unroll
                    for (int q = 0; q < 4; q++) {
                        float xv = (j == 0) ? xa[q].x : (j == 1) ? xa[q].y
                                 : (j == 2) ? xa[q].z : xa[q].w;
                        unsigned long long av = pack_dup(xv);
                        fma2(acc[half * 4 + q][0], av, w.x);
                        fma2(acc[half * 4 + q][1], av, w.y);
                    }
                }
            }
        }
        {
            ulonglong2 w = *reinterpret_cast<const ulonglong2*>(&Wc[24 * HID + tx * 4]);
#pragma unroll
            for (int q = 0; q < 8; q++) {
                unsigned long long av = pack_dup(Xs[(ty * 8 + q) * 28 + 24]);
                fma2(acc[q][0], av, w.x);
                fma2(acc[q][1], av, w.y);
            }
        }
    }

    __syncthreads();
    float* hsm = pool;                      // [128][65]
#pragma unroll
    for (int q = 0; q < 8; q++) {
        int p = ty * 8 + q;
        hsm[p * 65 + tx * 4 + 0] = fmaxf(lo32(acc[q][0]) + b1s[tx * 4 + 0], 0.f);
        hsm[p * 65 + tx * 4 + 1] = fmaxf(hi32(acc[q][0]) + b1s[tx * 4 + 1], 0.f);
        hsm[p * 65 + tx * 4 + 2] = fmaxf(lo32(acc[q][1]) + b1s[tx * 4 + 2], 0.f);
        hsm[p * 65 + tx * 4 + 3] = fmaxf(hi32(acc[q][1]) + b1s[tx * 4 + 3], 0.f);
    }
    __syncthreads();

    if (tid < 128) {
        float score = 0.f;
        const float* hp = &hsm[tid * 65];
#pragma unroll
        for (int j = 0; j < HID; j++) score = __fmaf_rn(hp[j], W2s[j], score);
        score += b2[0];
        g_sal[p0 + tid] = 1.f / (1.f + expf(-score));
    }
}

// ---------------------------------------------------------------------------
// K2: cumsum (shfl) + softmax with bit-exact tree reductions + radix-select
// with 8-copy histograms + ranking sort (unchanged from R11, which passed)
// ---------------------------------------------------------------------------
__global__ __launch_bounds__(1024)
void batch_kernel(float* __restrict__ ystar_out)
{
    __shared__ unsigned kv[Nq];
    __shared__ float    tsum[1024];
    __shared__ float    fred[32];
    __shared__ unsigned ured[32];
    __shared__ unsigned hC[8 * 256];
    __shared__ unsigned hA[256], hB[256];
    __shared__ unsigned selv[KEFF];
    __shared__ int      seli[KEFF];
    __shared__ int      ranks[KEFF];
    __shared__ float    sh_red;
    __shared__ unsigned sh_prefix, sh_krem, sh_gt;

    const int b = blockIdx.x, t = threadIdx.x;
    const int lane = t & 31, wid = t >> 5;

    float4 sl = *reinterpret_cast<const float4*>(&g_sal[(size_t)b * Nq + 4 * t]);
    float s0 = sl.x, s1 = sl.y, s2 = sl.z, s3 = sl.w;

    float l0 = s0, l1 = l0 + s1, l2 = l1 + s2, l3 = l2 + s3;
    float inc = l3;
#pragma unroll
    for (int off = 1; off < 32; off <<= 1) {
        float v = __shfl_up_sync(0xffffffffu, inc, off);
        if (lane >= off) inc += v;
    }
    if (lane == 31) fred[wid] = inc;
    __syncthreads();
    if (wid == 0) {
        float v = fred[lane], sc = v;
#pragma unroll
        for (int off = 1; off < 32; off <<= 1) {
            float u = __shfl_up_sync(0xffffffffu, sc, off);
            if (lane >= off) sc += u;
        }
        fred[lane] = sc - v;
    }
    __syncthreads();
    {
        float pre = fred[wid] + (inc - l3);
        const float invN = 1.f / (float)Nq;
        float4 c4;
        c4.x = (pre + l0) * invN; c4.y = (pre + l1) * invN;
        c4.z = (pre + l2) * invN; c4.w = (pre + l3) * invN;
        *reinterpret_cast<float4*>(&g_csal[(size_t)b * Nq + 4 * t]) = c4;
    }

    tsum[t] = fmaxf(fmaxf(s0, s1), fmaxf(s2, s3));
    __syncthreads();
#pragma unroll
    for (int off = 512; off >= 32; off >>= 1) {
        if (t < off) tsum[t] = fmaxf(tsum[t], tsum[t + off]);
        __syncthreads();
    }
    if (t < 32) {
        float v = tsum[t];
#pragma unroll
        for (int off = 16; off > 0; off >>= 1)
            v = fmaxf(v, __shfl_down_sync(0xffffffffu, v, off));
        if (t == 0) sh_red = v;
    }
    __syncthreads();
    const float mz = sh_red * 2.0f;
    float e0 = expf(s0 * 2.0f - mz);
    float e1 = expf(s1 * 2.0f - mz);
    float e2 = expf(s2 * 2.0f - mz);
    float e3 = expf(s3 * 2.0f - mz);
    __syncthreads();
    tsum[t] = (e0 + e1) + (e2 + e3);
    __syncthreads();
#pragma unroll
    for (int off = 512; off >= 32; off >>= 1) {
        if (t < off) tsum[t] = tsum[t] + tsum[t + off];
        __syncthreads();
    }
    if (t < 32) {
        float v = tsum[t];
#pragma unroll
        for (int off = 16; off > 0; off >>= 1)
            v = v + __shfl_down_sync(0xffffffffu, v, off);
        if (t == 0) sh_red = v;
    }
    if (t == 0) { sh_prefix = 0u; sh_krem = KEFF; }
    __syncthreads();
    const float S = sh_red;

    float y0 = e0 / S, y1 = e1 / S, y2 = e2 / S, y3 = e3 / S;
    {
        float4 y4; y4.x = y0; y4.y = y1; y4.z = y2; y4.w = y3;
        *reinterpret_cast<float4*>(&ystar_out[(size_t)b * Nq + 4 * t]) = y4;
    }
    kv[4 * t + 0] = __float_as_uint(y0);
    kv[4 * t + 1] = __float_as_uint(y1);
    kv[4 * t + 2] = __float_as_uint(y2);
    kv[4 * t + 3] = __float_as_uint(y3);
    __syncthreads();

#pragma unroll
    for (int round = 0; round < 4; round++) {
        const int shift = 24 - 8 * round;
        const unsigned pmask = (round == 0) ? 0u : (0xFFFFFFFFu << (32 - 8 * round));
        const unsigned pfx  = sh_prefix;
        const unsigned krem = sh_krem;
        hC[t] = 0u; hC[t + 1024] = 0u;
        __syncthreads();
        unsigned* myh = &hC[(t >> 7) << 8];
#pragma unroll
        for (int e = 0; e < 4; e++) {
            unsigned v = kv[4 * t + e];
            if ((v & pmask) == pfx) atomicAdd(&myh[(v >> shift) & 255], 1u);
        }
        __syncthreads();
        if (t < 256) {
            unsigned s = 0;
#pragma unroll
            for (int c = 0; c < 8; c++) s += hC[c * 256 + t];
            hA[t] = s;
        }
        __syncthreads();
        if (wid == 0) {
            unsigned loc[8], tot = 0;
#pragma unroll
            for (int j = 0; j < 8; j++) { loc[j] = hA[lane * 8 + j]; tot += loc[j]; }
            unsigned suf = tot;
#pragma unroll
            for (int off = 1; off < 32; off <<= 1) {
                unsigned v = __shfl_down_sync(0xffffffffu, suf, off);
                if (lane + off < 32) suf += v;
            }
            unsigned run = suf - tot;
#pragma unroll
            for (int j = 7; j >= 0; j--) { run += loc[j]; hB[lane * 8 + j] = run; }
        }
        __syncthreads();
        if (t < 256) {
            unsigned Sb = hB[t];
            unsigned Sn = (t == 255) ? 0u : hB[t + 1];
            if (Sb >= krem && Sn < krem) {
                sh_prefix = pfx | ((unsigned)t << shift);
                sh_krem   = krem - Sn;
            }
        }
        __syncthreads();
    }
    const unsigned T = sh_prefix;
    const unsigned need_eq = sh_krem;

    {
        unsigned c = 0;
#pragma unroll
        for (int e = 0; e < 4; e++) c += (kv[4 * t + e] > T);
        unsigned incu = c;
#pragma unroll
        for (int off = 1; off < 32; off <<= 1) {
            unsigned v = __shfl_up_sync(0xffffffffu, incu, off);
            if (lane >= off) incu += v;
        }
        if (lane == 31) ured[wid] = incu;
        __syncthreads();
        if (wid == 0) {
            unsigned v = ured[lane], sc = v;
#pragma unroll
            for (int off = 1; off < 32; off <<= 1) {
                unsigned u = __shfl_up_sync(0xffffffffu, sc, off);
                if (lane >= off) sc += u;
            }
            ured[lane] = sc - v;
        }
        __syncthreads();
        unsigned pos = ured[wid] + incu - c;
        if (t == 1023) sh_gt = pos + c;
#pragma unroll
        for (int e = 0; e < 4; e++) {
            int i = 4 * t + e;
            unsigned v = kv[i];
            if (v > T) { selv[pos] = v; seli[pos] = i; pos++; }
        }
        __syncthreads();
    }
    {
        const unsigned gt = sh_gt;
        unsigned c = 0;
#pragma unroll
        for (int e = 0; e < 4; e++) c += (kv[4 * t + e] == T);
        unsigned incu = c;
#pragma unroll
        for (int off = 1; off < 32; off <<= 1) {
            unsigned v = __shfl_up_sync(0xffffffffu, incu, off);
            if (lane >= off) incu += v;
        }
        if (lane == 31) ured[wid] = incu;
        __syncthreads();
        if (wid == 0) {
            unsigned v = ured[lane], sc = v;
#pragma unroll
            for (int off = 1; off < 32; off <<= 1) {
                unsigned u = __shfl_up_sync(0xffffffffu, sc, off);
                if (lane >= off) sc += u;
            }
            ured[lane] = sc - v;
        }
        __syncthreads();
        unsigned pos = ured[wid] + incu - c;
#pragma unroll
        for (int e = 0; e < 4; e++) {
            int i = 4 * t + e;
            if (kv[i] == T) {
                if (pos < need_eq) { selv[gt + pos] = T; seli[gt + pos] = i; }
                pos++;
            }
        }
        __syncthreads();
    }

    if (t < 256) ranks[t] = 0;
    __syncthreads();
    {
        const int i = t & 255, part = t >> 8;
        const unsigned vi = selv[i];
        const int ii = seli[i];
        int cnt = 0;
#pragma unroll 8
        for (int j = part * 64; j < part * 64 + 64; j++) {
            unsigned vj = selv[j];
            int ij = seli[j];
            cnt += (vj > vi) || (vj == vi && ij < ii);
        }
        if (cnt) atomicAdd(&ranks[i], cnt);
    }
    __syncthreads();
    if (t < 256) g_top[b * KEFF + ranks[t]] = seli[t];
}

// ---------------------------------------------------------------------------
// K3: warp-per-point gather + normalize + lift (unchanged)
// ---------------------------------------------------------------------------
__global__ __launch_bounds__(256)
void lift_kernel(const float* __restrict__ x,
                 const float* __restrict__ liftW, const float* __restrict__ liftb,
                 const float* __restrict__ mu,    const float* __restrict__ sigma)
{
    __shared__ float Ws[ADIM * KDIM];
    __shared__ float mus[ADIM], rs[ADIM], lbs[KDIM];
    __shared__ float wsh[8][ADIM];

    const int tid = threadIdx.x;
    for (int i = tid; i < (ADIM * KDIM) / 4; i += 256)
        reinterpret_cast<float4*>(Ws)[i] = reinterpret_cast<const float4*>(liftW)[i];
    if (tid < ADIM) { mus[tid] = mu[tid]; rs[tid] = 1.f / sigma[tid]; }
    if (tid < KDIM) lbs[tid] = liftb[tid];

    const int w = tid >> 5, l = tid & 31;
    const int b     = blockIdx.x >> 2;
    const int kbase = (blockIdx.x & 3) * 64;
    __syncthreads();

    for (int it = 0; it < 8; it++) {
        const int k   = kbase + it * 8 + w;
        const int idx = g_top[b * KEFF + k];
        const float* xr = x + ((size_t)b * Nq + idx) * IDIM;

        float v[4];
#pragma unroll
        for (int q = 0; q < 4; q++) {
            int a = q * 32 + l;
            float val;
            if (a < IDIM)       val = xr[a];
            else if (a == 125)  val = g_sal [(size_t)b * Nq + idx];
            else if (a == 126)  val = (float)idx * (1.f / (float)(Nq - 1));
            else                val = g_csal[(size_t)b * Nq + idx];
            v[q] = val;
        }
        float ss = (v[0] * v[0] + v[1] * v[1]) + (v[2] * v[2] + v[3] * v[3]);
#pragma unroll
        for (int o = 16; o > 0; o >>= 1) ss += __shfl_xor_sync(0xffffffffu, ss, o);
        const float sc = 1.f / (sqrtf(ss) + EPSq);
#pragma unroll
        for (int q = 0; q < 4; q++) {
            int a = q * 32 + l;
            wsh[w][a] = (v[q] * sc - mus[a]) * rs[a];
        }
        __syncwarp();

        unsigned long long acc = pack2(lbs[2 * l], lbs[2 * l + 1]);
#pragma unroll 8
        for (int a = 0; a < ADIM; a++) {
            unsigned long long wpair =
                *reinterpret_cast<const unsigned long long*>(&Ws[a * KDIM + 2 * l]);
            fma2(acc, pack_dup(wsh[w][a]), wpair);
        }
        float2 o; o.x = lo32(acc); o.y = hi32(acc);
        *reinterpret_cast<float2*>(&g_cloud[((size_t)b * KEFF + k) * KDIM + 2 * l]) = o;
        __syncwarp();
    }
}

// ---------------------------------------------------------------------------
// K4: tokens via fp16 mma.sync.m16n8k16 (fp32 accum).
// CTA = 128 rows x 128 cols, 256 threads; warp = 16 rows x 128 cols
// = 16 m16n8 tiles x 4 k-steps.
// As2[r][j] = half2(A[r][2j], A[r][2j+1]), 32 j's, pad 36  (18.4 KB)
// Bs2[p][n] = half2(B[2p][n], B[2p+1][n]),  32 p's, pad 136 (17.4 KB)
// All frag loads scalar LDS.32, conflict-free (R10-verified bank pattern).
// ---------------------------------------------------------------------------
#define PADA2 36
#define PADB2 136
#define TKA2_WORDS (128 * PADA2)
#define TK_SMEM ((TKA2_WORDS + 32 * PADB2) * 4)

__global__ __launch_bounds__(256, 3)
void tokens_mma_kernel(const float* __restrict__ projW, const float* __restrict__ projb,
                       float* __restrict__ out)
{
    extern __shared__ uint32_t sm[];
    uint32_t* As2 = sm;                     // [128][PADA2]
    uint32_t* Bs2 = sm + TKA2_WORDS;        // [32][PADB2]

    const int tid = threadIdx.x;
    const int warp = tid >> 5, lane = tid & 31;
    const int qid = lane >> 2, qtd = lane & 3;
    const int r0 = blockIdx.y * 128;
    const int d0 = blockIdx.x * 128;

    // stage A: cloud rows fp32 -> half2 pairs (coalesced float4 reads)
    for (int i = tid; i < 2048; i += 256) {
        int r = i >> 4, c4 = i & 15;
        float4 v = *reinterpret_cast<const float4*>(
            &g_cloud[(size_t)(r0 + r) * KDIM + c4 * 4]);
        uint32_t* dst = &As2[r * PADA2 + c4 * 2];
        dst[0] = h2pack(v.x, v.y);
        dst[1] = h2pack(v.z, v.w);
    }
    // stage B: pair-rows of projW -> half2(k even, k odd) (coalesced reads)
    for (int i = tid; i < 1024; i += 256) {
        int pr = i >> 5, n4 = i & 31;                    // pair-row, float4 col
        const float4 ve = *reinterpret_cast<const float4*>(
            &projW[(size_t)(2 * pr) * DMOD + d0 + n4 * 4]);
        const float4 vo = *reinterpret_cast<const float4*>(
            &projW[(size_t)(2 * pr + 1) * DMOD + d0 + n4 * 4]);
        uint32_t* dst = &Bs2[pr * PADB2 + n4 * 4];
        dst[0] = h2pack(ve.x, vo.x);
        dst[1] = h2pack(ve.y, vo.y);
        dst[2] = h2pack(ve.z, vo.z);
        dst[3] = h2pack(ve.w, vo.w);
    }
    __syncthreads();

    float c[16][4];
#pragma unroll
    for (int nt = 0; nt < 16; nt++)
#pragma unroll
        for (int j = 0; j < 4; j++) c[nt][j] = 0.f;

#pragma unroll
    for (int ks = 0; ks < 4; ks++) {
        const int j0 = ks * 8;                           // half2-pair index base
        const uint32_t* arow = &As2[(warp * 16 + qid) * PADA2 + j0 + qtd];
        uint32_t a0 = arow[0];                           // row, k 2qtd..+1
        uint32_t a1 = arow[8 * PADA2];                   // row+8
        uint32_t a2 = arow[4];                           // row, k+8
        uint32_t a3 = arow[8 * PADA2 + 4];               // row+8, k+8
        const uint32_t* brow = &Bs2[(j0 + qtd) * PADB2 + qid];
#pragma unroll
        for (int nt = 0; nt < 16; nt++) {
            uint32_t b0 = brow[nt * 8];                  // k 2qtd..+1, col qid
            uint32_t b1 = brow[4 * PADB2 + nt * 8];      // k+8
            asm volatile(
                "mma.sync.aligned.m16n8k16.row.col.f32.f16.f16.f32 "
                "{%0,%1,%2,%3}, {%4,%5,%6,%7}, {%8,%9}, {%0,%1,%2,%3};"
                : "+f"(c[nt][0]), "+f"(c[nt][1]), "+f"(c[nt][2]), "+f"(c[nt][3])
                : "r"(a0), "r"(a1), "r"(a2), "r"(a3), "r"(b0), "r"(b1));
        }
    }

    // epilogue: c0,c1 -> (row, col..col+1); c2,c3 -> (row+8, ...)
    const size_t rowA = (size_t)(r0 + warp * 16 + qid);
#pragma unroll
    for (int nt = 0; nt < 16; nt++) {
        const int col = d0 + nt * 8 + qtd * 2;
        const float pb0 = projb[col], pb1 = projb[col + 1];
        float2 o1, o2;
        o1.x = c[nt][0] + pb0; o1.y = c[nt][1] + pb1;
        o2.x = c[nt][2] + pb0; o2.y = c[nt][3] + pb1;
        *reinterpret_cast<float2*>(&out[rowA * DMOD + col]) = o1;
        *reinterpret_cast<float2*>(&out[(rowA + 8) * DMOD + col]) = o2;
    }
}

// ---------------------------------------------------------------------------
extern "C" void kernel_launch(void* const* d_in, const int* in_sizes, int n_in,
                              void* d_out, int out_size)
{
    const float* x     = (const float*)d_in[0];
    const float* W1    = (const float*)d_in[1];
    const float* b1    = (const float*)d_in[2];
    const float* W2    = (const float*)d_in[3];
    const float* b2    = (const float*)d_in[4];
    const float* liftW = (const float*)d_in[5];
    const float* liftb = (const float*)d_in[6];
    const float* mu    = (const float*)d_in[7];
    const float* sigma = (const float*)d_in[8];
    const float* projW = (const float*)d_in[9];
    const float* projb = (const float*)d_in[10];

    float* out    = (float*)d_out;
    float* tokens = out;                                   // [32,256,1024]
    float* ystar  = out + (size_t)Bq * KEFF * DMOD;        // [32,4096]

    cudaFuncSetAttribute(tokens_mma_kernel,
                         cudaFuncAttributeMaxDynamicSharedMemorySize, TK_SMEM);

    mlp_kernel  <<<(Bq * Nq) / 128, 256>>>(x, W1, b1, W2, b2);
    batch_kernel<<<Bq, 1024>>>(ystar);
    lift_kernel <<<Bq * 4, 256>>>(x, liftW, liftb, mu, sigma);
    tokens_mma_kernel<<<dim3(DMOD / 128, (Bq * KEFF) / 128), 256, TK_SMEM>>>(
        projW, projb, tokens);
}

// round 14
// speedup vs baseline: 1.4833x; 1.4833x over previous
#include <cuda_runtime.h>
#include <cuda_bf16.h>
#include <cuda_fp16.h>
#include <cstdint>

// ---------------------------------------------------------------------------
// EncoderSaliencySelection, GB300 sm_103a (PTX target compute_103: no tcgen05;
// tokens GEMM uses fp16 mma.sync.m16n8k16, fp32 accumulate)
// ---------------------------------------------------------------------------

#define Bq   32
#define Nq   4096
#define IDIM 125
#define ADIM 128
#define KDIM 64
#define DMOD 1024
#define HID  64
#define KEFF 256
#define EPSq 1e-6f

__device__ float g_sal [Bq * Nq];
__device__ float g_csal[Bq * Nq];
__device__ int   g_top [Bq * KEFF];
__device__ float g_cloud[Bq * KEFF * KDIM];

// packed f32x2 helpers (element-wise exact)
__device__ __forceinline__ unsigned long long pack_dup(float v) {
    unsigned long long r;
    asm("mov.b64 %0, {%1, %1};" : "=l"(r) : "f"(v));
    return r;
}
__device__ __forceinline__ unsigned long long pack2(float a, float b) {
    unsigned long long r;
    asm("mov.b64 %0, {%1, %2};" : "=l"(r) : "f"(a), "f"(b));
    return r;
}
__device__ __forceinline__ void fma2(unsigned long long& acc,
                                     unsigned long long a, unsigned long long b) {
    asm("fma.rn.f32x2 %0, %1, %2, %0;" : "+l"(acc) : "l"(a), "l"(b));
}
__device__ __forceinline__ float lo32(unsigned long long v) {
    return __uint_as_float((unsigned)(v & 0xffffffffull));
}
__device__ __forceinline__ float hi32(unsigned long long v) {
    return __uint_as_float((unsigned)(v >> 32));
}
// pack (lo, hi) floats -> half2 in one cvt
__device__ __forceinline__ uint32_t h2pack(float lo, float hi) {
    uint32_t r;
    asm("cvt.rn.f16x2.f32 %0, %1, %2;" : "=r"(r) : "f"(hi), "f"(lo));
    return r;
}

// ---------------------------------------------------------------------------
// K1: MLP scorer tiled GEMM (unchanged from R8/R10 passing version)
// ---------------------------------------------------------------------------
#define CHUNK 25
__global__ __launch_bounds__(256)
void mlp_kernel(const float* __restrict__ x,  const float* __restrict__ W1,
                const float* __restrict__ b1, const float* __restrict__ W2,
                const float* __restrict__ b2)
{
    __shared__ float pool[128 * 65];
    __shared__ float b1s[HID], W2s[HID];

    float* Xs = pool;                       // [128][28]
    float* Wc = pool + 128 * 28;            // [25][64]

    const int tid = threadIdx.x;
    if (tid < HID) { b1s[tid] = b1[tid]; W2s[tid] = W2[tid]; }

    const int p0 = blockIdx.x * 128;
    const int tx = tid & 15;
    const int ty = tid >> 4;

    unsigned long long acc[8][2];
#pragma unroll
    for (int q = 0; q < 8; q++) { acc[q][0] = 0ull; acc[q][1] = 0ull; }

    for (int cc = 0; cc < 5; cc++) {
        __syncthreads();
        for (int i = tid; i < (CHUNK * HID) / 4; i += 256)
            reinterpret_cast<float4*>(Wc)[i] =
                reinterpret_cast<const float4*>(W1 + cc * CHUNK * HID)[i];
        for (int i = tid; i < 128 * CHUNK; i += 256) {
            int p = i / CHUNK, c = i - p * CHUNK;
            Xs[p * 28 + c] = x[(size_t)(p0 + p) * IDIM + cc * CHUNK + c];
        }
        __syncthreads();

#pragma unroll
        for (int c4 = 0; c4 < 6; c4++) {
#pragma unroll
            for (int half = 0; half < 2; half++) {
                float4 xa[4];
#pragma unroll
                for (int q = 0; q < 4; q++)
                    xa[q] = *reinterpret_cast<const float4*>(
                        &Xs[(ty * 8 + half * 4 + q) * 28 + c4 * 4]);
#pragma unroll
                for (int j = 0; j < 4; j++) {
                    ulonglong2 w = *reinterpret_cast<const ulonglong2*>(
                        &Wc[(c4 * 4 + j) * HID + tx * 4]);
#pragma unroll
                    for (int q = 0; q < 4; q++) {
                        float xv = (j == 0) ? xa[q].x : (j == 1) ? xa[q].y
                                 : (j == 2) ? xa[q].z : xa[q].w;
                        unsigned long long av = pack_dup(xv);
                        fma2(acc[half * 4 + q][0], av, w.x);
                        fma2(acc[half * 4 + q][1], av, w.y);
                    }
                }
            }
        }
        {
            ulonglong2 w = *reinterpret_cast<const ulonglong2*>(&Wc[24 * HID + tx * 4]);
#pragma unroll
            for (int q = 0; q < 8; q++) {
                unsigned long long av = pack_dup(Xs[(ty * 8 + q) * 28 + 24]);
                fma2(acc[q][0], av, w.x);
                fma2(acc[q][1], av, w.y);
            }
        }
    }

    __syncthreads();
    float* hsm = pool;                      // [128][65]
#pragma unroll
    for (int q = 0; q < 8; q++) {
        int p = ty * 8 + q;
        hsm[p * 65 + tx * 4 + 0] = fmaxf(lo32(acc[q][0]) + b1s[tx * 4 + 0], 0.f);
        hsm[p * 65 + tx * 4 + 1] = fmaxf(hi32(acc[q][0]) + b1s[tx * 4 + 1], 0.f);
        hsm[p * 65 + tx * 4 + 2] = fmaxf(lo32(acc[q][1]) + b1s[tx * 4 + 2], 0.f);
        hsm[p * 65 + tx * 4 + 3] = fmaxf(hi32(acc[q][1]) + b1s[tx * 4 + 3], 0.f);
    }
    __syncthreads();

    if (tid < 128) {
        float score = 0.f;
        const float* hp = &hsm[tid * 65];
#pragma unroll
        for (int j = 0; j < HID; j++) score = __fmaf_rn(hp[j], W2s[j], score);
        score += b2[0];
        g_sal[p0 + tid] = 1.f / (1.f + expf(-score));
    }
}

// ---------------------------------------------------------------------------
// K2: cumsum (shfl) + softmax with bit-exact tree reductions + radix-select
// with 8-copy histograms + ranking sort (unchanged from R11/R13, passing)
// ---------------------------------------------------------------------------
__global__ __launch_bounds__(1024)
void batch_kernel(float* __restrict__ ystar_out)
{
    __shared__ unsigned kv[Nq];
    __shared__ float    tsum[1024];
    __shared__ float    fred[32];
    __shared__ unsigned ured[32];
    __shared__ unsigned hC[8 * 256];
    __shared__ unsigned hA[256], hB[256];
    __shared__ unsigned selv[KEFF];
    __shared__ int      seli[KEFF];
    __shared__ int      ranks[KEFF];
    __shared__ float    sh_red;
    __shared__ unsigned sh_prefix, sh_krem, sh_gt;

    const int b = blockIdx.x, t = threadIdx.x;
    const int lane = t & 31, wid = t >> 5;

    float4 sl = *reinterpret_cast<const float4*>(&g_sal[(size_t)b * Nq + 4 * t]);
    float s0 = sl.x, s1 = sl.y, s2 = sl.z, s3 = sl.w;

    float l0 = s0, l1 = l0 + s1, l2 = l1 + s2, l3 = l2 + s3;
    float inc = l3;
#pragma unroll
    for (int off = 1; off < 32; off <<= 1) {
        float v = __shfl_up_sync(0xffffffffu, inc, off);
        if (lane >= off) inc += v;
    }
    if (lane == 31) fred[wid] = inc;
    __syncthreads();
    if (wid == 0) {
        float v = fred[lane], sc = v;
#pragma unroll
        for (int off = 1; off < 32; off <<= 1) {
            float u = __shfl_up_sync(0xffffffffu, sc, off);
            if (lane >= off) sc += u;
        }
        fred[lane] = sc - v;
    }
    __syncthreads();
    {
        float pre = fred[wid] + (inc - l3);
        const float invN = 1.f / (float)Nq;
        float4 c4;
        c4.x = (pre + l0) * invN; c4.y = (pre + l1) * invN;
        c4.z = (pre + l2) * invN; c4.w = (pre + l3) * invN;
        *reinterpret_cast<float4*>(&g_csal[(size_t)b * Nq + 4 * t]) = c4;
    }

    tsum[t] = fmaxf(fmaxf(s0, s1), fmaxf(s2, s3));
    __syncthreads();
#pragma unroll
    for (int off = 512; off >= 32; off >>= 1) {
        if (t < off) tsum[t] = fmaxf(tsum[t], tsum[t + off]);
        __syncthreads();
    }
    if (t < 32) {
        float v = tsum[t];
#pragma unroll
        for (int off = 16; off > 0; off >>= 1)
            v = fmaxf(v, __shfl_down_sync(0xffffffffu, v, off));
        if (t == 0) sh_red = v;
    }
    __syncthreads();
    const float mz = sh_red * 2.0f;
    float e0 = expf(s0 * 2.0f - mz);
    float e1 = expf(s1 * 2.0f - mz);
    float e2 = expf(s2 * 2.0f - mz);
    float e3 = expf(s3 * 2.0f - mz);
    __syncthreads();
    tsum[t] = (e0 + e1) + (e2 + e3);
    __syncthreads();
#pragma unroll
    for (int off = 512; off >= 32; off >>= 1) {
        if (t < off) tsum[t] = tsum[t] + tsum[t + off];
        __syncthreads();
    }
    if (t < 32) {
        float v = tsum[t];
#pragma unroll
        for (int off = 16; off > 0; off >>= 1)
            v = v + __shfl_down_sync(0xffffffffu, v, off);
        if (t == 0) sh_red = v;
    }
    if (t == 0) { sh_prefix = 0u; sh_krem = KEFF; }
    __syncthreads();
    const float S = sh_red;

    float y0 = e0 / S, y1 = e1 / S, y2 = e2 / S, y3 = e3 / S;
    {
        float4 y4; y4.x = y0; y4.y = y1; y4.z = y2; y4.w = y3;
        *reinterpret_cast<float4*>(&ystar_out[(size_t)b * Nq + 4 * t]) = y4;
    }
    kv[4 * t + 0] = __float_as_uint(y0);
    kv[4 * t + 1] = __float_as_uint(y1);
    kv[4 * t + 2] = __float_as_uint(y2);
    kv[4 * t + 3] = __float_as_uint(y3);
    __syncthreads();

#pragma unroll
    for (int round = 0; round < 4; round++) {
        const int shift = 24 - 8 * round;
        const unsigned pmask = (round == 0) ? 0u : (0xFFFFFFFFu << (32 - 8 * round));
        const unsigned pfx  = sh_prefix;
        const unsigned krem = sh_krem;
        hC[t] = 0u; hC[t + 1024] = 0u;
        __syncthreads();
        unsigned* myh = &hC[(t >> 7) << 8];
#pragma unroll
        for (int e = 0; e < 4; e++) {
            unsigned v = kv[4 * t + e];
            if ((v & pmask) == pfx) atomicAdd(&myh[(v >> shift) & 255], 1u);
        }
        __syncthreads();
        if (t < 256) {
            unsigned s = 0;
#pragma unroll
            for (int c = 0; c < 8; c++) s += hC[c * 256 + t];
            hA[t] = s;
        }
        __syncthreads();
        if (wid == 0) {
            unsigned loc[8], tot = 0;
#pragma unroll
            for (int j = 0; j < 8; j++) { loc[j] = hA[lane * 8 + j]; tot += loc[j]; }
            unsigned suf = tot;
#pragma unroll
            for (int off = 1; off < 32; off <<= 1) {
                unsigned v = __shfl_down_sync(0xffffffffu, suf, off);
                if (lane + off < 32) suf += v;
            }
            unsigned run = suf - tot;
#pragma unroll
            for (int j = 7; j >= 0; j--) { run += loc[j]; hB[lane * 8 + j] = run; }
        }
        __syncthreads();
        if (t < 256) {
            unsigned Sb = hB[t];
            unsigned Sn = (t == 255) ? 0u : hB[t + 1];
            if (Sb >= krem && Sn < krem) {
                sh_prefix = pfx | ((unsigned)t << shift);
                sh_krem   = krem - Sn;
            }
        }
        __syncthreads();
    }
    const unsigned T = sh_prefix;
    const unsigned need_eq = sh_krem;

    {
        unsigned c = 0;
#pragma unroll
        for (int e = 0; e < 4; e++) c += (kv[4 * t + e] > T);
        unsigned incu = c;
#pragma unroll
        for (int off = 1; off < 32; off <<= 1) {
            unsigned v = __shfl_up_sync(0xffffffffu, incu, off);
            if (lane >= off) incu += v;
        }
        if (lane == 31) ured[wid] = incu;
        __syncthreads();
        if (wid == 0) {
            unsigned v = ured[lane], sc = v;
#pragma unroll
            for (int off = 1; off < 32; off <<= 1) {
                unsigned u = __shfl_up_sync(0xffffffffu, sc, off);
                if (lane >= off) sc += u;
            }
            ured[lane] = sc - v;
        }
        __syncthreads();
        unsigned pos = ured[wid] + incu - c;
        if (t == 1023) sh_gt = pos + c;
#pragma unroll
        for (int e = 0; e < 4; e++) {
            int i = 4 * t + e;
            unsigned v = kv[i];
            if (v > T) { selv[pos] = v; seli[pos] = i; pos++; }
        }
        __syncthreads();
    }
    {
        const unsigned gt = sh_gt;
        unsigned c = 0;
#pragma unroll
        for (int e = 0; e < 4; e++) c += (kv[4 * t + e] == T);
        unsigned incu = c;
#pragma unroll
        for (int off = 1; off < 32; off <<= 1) {
            unsigned v = __shfl_up_sync(0xffffffffu, incu, off);
            if (lane >= off) incu += v;
        }
        if (lane == 31) ured[wid] = incu;
        __syncthreads();
        if (wid == 0) {
            unsigned v = ured[lane], sc = v;
#pragma unroll
            for (int off = 1; off < 32; off <<= 1) {
                unsigned u = __shfl_up_sync(0xffffffffu, sc, off);
                if (lane >= off) sc += u;
            }
            ured[lane] = sc - v;
        }
        __syncthreads();
        unsigned pos = ured[wid] + incu - c;
#pragma unroll
        for (int e = 0; e < 4; e++) {
            int i = 4 * t + e;
            if (kv[i] == T) {
                if (pos < need_eq) { selv[gt + pos] = T; seli[gt + pos] = i; }
                pos++;
            }
        }
        __syncthreads();
    }

    if (t < 256) ranks[t] = 0;
    __syncthreads();
    {
        const int i = t & 255, part = t >> 8;
        const unsigned vi = selv[i];
        const int ii = seli[i];
        int cnt = 0;
#pragma unroll 8
        for (int j = part * 64; j < part * 64 + 64; j++) {
            unsigned vj = selv[j];
            int ij = seli[j];
            cnt += (vj > vi) || (vj == vi && ij < ii);
        }
        if (cnt) atomicAdd(&ranks[i], cnt);
    }
    __syncthreads();
    if (t < 256) g_top[b * KEFF + ranks[t]] = seli[t];
}

// ---------------------------------------------------------------------------
// K3: warp-per-point gather + normalize + lift (unchanged)
// ---------------------------------------------------------------------------
__global__ __launch_bounds__(256)
void lift_kernel(const float* __restrict__ x,
                 const float* __restrict__ liftW, const float* __restrict__ liftb,
                 const float* __restrict__ mu,    const float* __restrict__ sigma)
{
    __shared__ float Ws[ADIM * KDIM];
    __shared__ float mus[ADIM], rs[ADIM], lbs[KDIM];
    __shared__ float wsh[8][ADIM];

    const int tid = threadIdx.x;
    for (int i = tid; i < (ADIM * KDIM) / 4; i += 256)
        reinterpret_cast<float4*>(Ws)[i] = reinterpret_cast<const float4*>(liftW)[i];
    if (tid < ADIM) { mus[tid] = mu[tid]; rs[tid] = 1.f / sigma[tid]; }
    if (tid < KDIM) lbs[tid] = liftb[tid];

    const int w = tid >> 5, l = tid & 31;
    const int b     = blockIdx.x >> 2;
    const int kbase = (blockIdx.x & 3) * 64;
    __syncthreads();

    for (int it = 0; it < 8; it++) {
        const int k   = kbase + it * 8 + w;
        const int idx = g_top[b * KEFF + k];
        const float* xr = x + ((size_t)b * Nq + idx) * IDIM;

        float v[4];
#pragma unroll
        for (int q = 0; q < 4; q++) {
            int a = q * 32 + l;
            float val;
            if (a < IDIM)       val = xr[a];
            else if (a == 125)  val = g_sal [(size_t)b * Nq + idx];
            else if (a == 126)  val = (float)idx * (1.f / (float)(Nq - 1));
            else                val = g_csal[(size_t)b * Nq + idx];
            v[q] = val;
        }
        float ss = (v[0] * v[0] + v[1] * v[1]) + (v[2] * v[2] + v[3] * v[3]);
#pragma unroll
        for (int o = 16; o > 0; o >>= 1) ss += __shfl_xor_sync(0xffffffffu, ss, o);
        const float sc = 1.f / (sqrtf(ss) + EPSq);
#pragma unroll
        for (int q = 0; q < 4; q++) {
            int a = q * 32 + l;
            wsh[w][a] = (v[q] * sc - mus[a]) * rs[a];
        }
        __syncwarp();

        unsigned long long acc = pack2(lbs[2 * l], lbs[2 * l + 1]);
#pragma unroll 8
        for (int a = 0; a < ADIM; a++) {
            unsigned long long wpair =
                *reinterpret_cast<const unsigned long long*>(&Ws[a * KDIM + 2 * l]);
            fma2(acc, pack_dup(wsh[w][a]), wpair);
        }
        float2 o; o.x = lo32(acc); o.y = hi32(acc);
        *reinterpret_cast<float2*>(&g_cloud[((size_t)b * KEFF + k) * KDIM + 2 * l]) = o;
        __syncwarp();
    }
}

// ---------------------------------------------------------------------------
// K4: tokens via fp16 mma.sync.m16n8k16 (fp32 accum), occupancy-tuned.
// CTA = 128 rows x 64 cols, 256 threads; warp = 16 rows x 64 cols
// = 8 m16n8 tiles x 4 k-steps. regs ~55 -> 4 CTAs/SM (32 warps).
// As2[r][j] = half2(A[r][2j], A[r][2j+1]), 32 j's, pad 36   (18.4 KB)
// Bs2[p][n] = half2(B[2p][n], B[2p+1][n]), 32 p's, pad 72   ( 9.2 KB)
// Frag LDS bank math: A (qid*4+qtd) mod 32, B (qtd*8+qid) mod 32: both
// 32 distinct banks -> conflict-free.
// ---------------------------------------------------------------------------
#define PADA2 36
#define PADB2 72
#define TKA2_WORDS (128 * PADA2)
#define TK_SMEM ((TKA2_WORDS + 32 * PADB2) * 4)

__global__ __launch_bounds__(256, 4)
void tokens_mma_kernel(const float* __restrict__ projW, const float* __restrict__ projb,
                       float* __restrict__ out)
{
    extern __shared__ uint32_t sm[];
    uint32_t* As2 = sm;                     // [128][PADA2]
    uint32_t* Bs2 = sm + TKA2_WORDS;        // [32][PADB2]

    const int tid = threadIdx.x;
    const int warp = tid >> 5, lane = tid & 31;
    const int qid = lane >> 2, qtd = lane & 3;
    const int r0 = blockIdx.y * 128;
    const int d0 = blockIdx.x * 64;

    // stage A: cloud rows fp32 -> half2 pairs (coalesced float4 reads)
    for (int i = tid; i < 2048; i += 256) {
        int r = i >> 4, c4 = i & 15;
        float4 v = *reinterpret_cast<const float4*>(
            &g_cloud[(size_t)(r0 + r) * KDIM + c4 * 4]);
        uint32_t* dst = &As2[r * PADA2 + c4 * 2];
        dst[0] = h2pack(v.x, v.y);
        dst[1] = h2pack(v.z, v.w);
    }
    // stage B: pair-rows of projW -> half2(k even, k odd) (coalesced reads)
    for (int i = tid; i < 512; i += 256) {
        int pr = i >> 4, n4 = i & 15;                    // pair-row, float4 col
        const float4 ve = *reinterpret_cast<const float4*>(
            &projW[(size_t)(2 * pr) * DMOD + d0 + n4 * 4]);
        const float4 vo = *reinterpret_cast<const float4*>(
            &projW[(size_t)(2 * pr + 1) * DMOD + d0 + n4 * 4]);
        uint32_t* dst = &Bs2[pr * PADB2 + n4 * 4];
        dst[0] = h2pack(ve.x, vo.x);
        dst[1] = h2pack(ve.y, vo.y);
        dst[2] = h2pack(ve.z, vo.z);
        dst[3] = h2pack(ve.w, vo.w);
    }
    __syncthreads();

    float c[8][4];
#pragma unroll
    for (int nt = 0; nt < 8; nt++)
#pragma unroll
        for (int j = 0; j < 4; j++) c[nt][j] = 0.f;

#pragma unroll
    for (int ks = 0; ks < 4; ks++) {
        const int j0 = ks * 8;                           // half2-pair index base
        const uint32_t* arow = &As2[(warp * 16 + qid) * PADA2 + j0 + qtd];
        uint32_t a0 = arow[0];                           // row, k 2qtd..+1
        uint32_t a1 = arow[8 * PADA2];                   // row+8
        uint32_t a2 = arow[4];                           // row, k+8
        uint32_t a3 = arow[8 * PADA2 + 4];               // row+8, k+8
        const uint32_t* brow = &Bs2[(j0 + qtd) * PADB2 + qid];
#pragma unroll
        for (int nt = 0; nt < 8; nt++) {
            uint32_t b0 = brow[nt * 8];                  // k 2qtd..+1, col qid
            uint32_t b1 = brow[4 * PADB2 + nt * 8];      // k+8
            asm volatile(
                "mma.sync.aligned.m16n8k16.row.col.f32.f16.f16.f32 "
                "{%0,%1,%2,%3}, {%4,%5,%6,%7}, {%8,%9}, {%0,%1,%2,%3};"
                : "+f"(c[nt][0]), "+f"(c[nt][1]), "+f"(c[nt][2]), "+f"(c[nt][3])
                : "r"(a0), "r"(a1), "r"(a2), "r"(a3), "r"(b0), "r"(b1));
        }
    }

    // epilogue: c0,c1 -> (row, col..col+1); c2,c3 -> (row+8, ...)
    const size_t rowA = (size_t)(r0 + warp * 16 + qid);
#pragma unroll
    for (int nt = 0; nt < 8; nt++) {
        const int col = d0 + nt * 8 + qtd * 2;
        const float pb0 = projb[col], pb1 = projb[col + 1];
        float2 o1, o2;
        o1.x = c[nt][0] + pb0; o1.y = c[nt][1] + pb1;
        o2.x = c[nt][2] + pb0; o2.y = c[nt][3] + pb1;
        *reinterpret_cast<float2*>(&out[rowA * DMOD + col]) = o1;
        *reinterpret_cast<float2*>(&out[(rowA + 8) * DMOD + col]) = o2;
    }
}

// ---------------------------------------------------------------------------
extern "C" void kernel_launch(void* const* d_in, const int* in_sizes, int n_in,
                              void* d_out, int out_size)
{
    const float* x     = (const float*)d_in[0];
    const float* W1    = (const float*)d_in[1];
    const float* b1    = (const float*)d_in[2];
    const float* W2    = (const float*)d_in[3];
    const float* b2    = (const float*)d_in[4];
    const float* liftW = (const float*)d_in[5];
    const float* liftb = (const float*)d_in[6];
    const float* mu    = (const float*)d_in[7];
    const float* sigma = (const float*)d_in[8];
    const float* projW = (const float*)d_in[9];
    const float* projb = (const float*)d_in[10];

    float* out    = (float*)d_out;
    float* tokens = out;                                   // [32,256,1024]
    float* ystar  = out + (size_t)Bq * KEFF * DMOD;        // [32,4096]

    cudaFuncSetAttribute(tokens_mma_kernel,
                         cudaFuncAttributeMaxDynamicSharedMemorySize, TK_SMEM);

    mlp_kernel  <<<(Bq * Nq) / 128, 256>>>(x, W1, b1, W2, b2);
    batch_kernel<<<Bq, 1024>>>(ystar);
    lift_kernel <<<Bq * 4, 256>>>(x, liftW, liftb, mu, sigma);
    tokens_mma_kernel<<<dim3(DMOD / 64, (Bq * KEFF) / 128), 256, TK_SMEM>>>(
        projW, projb, tokens);
}

// round 15
// speedup vs baseline: 1.4841x; 1.0005x over previous
#include <cuda_runtime.h>
#include <cuda_bf16.h>
#include <cuda_fp16.h>
#include <cstdint>

// ---------------------------------------------------------------------------
// EncoderSaliencySelection, GB300 sm_103a (PTX target compute_103: no tcgen05;
// tokens GEMM uses fp16 mma.sync.m16n8k16 + ldmatrix, fp32 accumulate)
// ---------------------------------------------------------------------------

#define Bq   32
#define Nq   4096
#define IDIM 125
#define ADIM 128
#define KDIM 64
#define DMOD 1024
#define HID  64
#define KEFF 256
#define EPSq 1e-6f

__device__ float g_sal [Bq * Nq];
__device__ float g_csal[Bq * Nq];
__device__ int   g_top [Bq * KEFF];
__device__ float g_cloud[Bq * KEFF * KDIM];

// packed f32x2 helpers (element-wise exact)
__device__ __forceinline__ unsigned long long pack_dup(float v) {
    unsigned long long r;
    asm("mov.b64 %0, {%1, %1};" : "=l"(r) : "f"(v));
    return r;
}
__device__ __forceinline__ unsigned long long pack2(float a, float b) {
    unsigned long long r;
    asm("mov.b64 %0, {%1, %2};" : "=l"(r) : "f"(a), "f"(b));
    return r;
}
__device__ __forceinline__ void fma2(unsigned long long& acc,
                                     unsigned long long a, unsigned long long b) {
    asm("fma.rn.f32x2 %0, %1, %2, %0;" : "+l"(acc) : "l"(a), "l"(b));
}
__device__ __forceinline__ float lo32(unsigned long long v) {
    return __uint_as_float((unsigned)(v & 0xffffffffull));
}
__device__ __forceinline__ float hi32(unsigned long long v) {
    return __uint_as_float((unsigned)(v >> 32));
}
// pack (lo, hi) floats -> half2 in one cvt
__device__ __forceinline__ uint32_t h2pack(float lo, float hi) {
    uint32_t r;
    asm("cvt.rn.f16x2.f32 %0, %1, %2;" : "=r"(r) : "f"(hi), "f"(lo));
    return r;
}
__device__ __forceinline__ uint32_t smem_u32(const void* p) {
    uint32_t a;
    asm("{ .reg .u64 t; cvta.to.shared.u64 t, %1; cvt.u32.u64 %0, t; }"
        : "=r"(a) : "l"(p));
    return a;
}
__device__ __forceinline__ void ldsm_x4(uint32_t& r0, uint32_t& r1,
                                        uint32_t& r2, uint32_t& r3, uint32_t addr) {
    asm volatile("ldmatrix.sync.aligned.m8n8.x4.shared.b16 {%0,%1,%2,%3}, [%4];"
                 : "=r"(r0), "=r"(r1), "=r"(r2), "=r"(r3) : "r"(addr));
}

// ---------------------------------------------------------------------------
// K1: MLP scorer tiled GEMM (unchanged from R8/R14 passing version)
// ---------------------------------------------------------------------------
#define CHUNK 25
__global__ __launch_bounds__(256)
void mlp_kernel(const float* __restrict__ x,  const float* __restrict__ W1,
                const float* __restrict__ b1, const float* __restrict__ W2,
                const float* __restrict__ b2)
{
    __shared__ float pool[128 * 65];
    __shared__ float b1s[HID], W2s[HID];

    float* Xs = pool;                       // [128][28]
    float* Wc = pool + 128 * 28;            // [25][64]

    const int tid = threadIdx.x;
    if (tid < HID) { b1s[tid] = b1[tid]; W2s[tid] = W2[tid]; }

    const int p0 = blockIdx.x * 128;
    const int tx = tid & 15;
    const int ty = tid >> 4;

    unsigned long long acc[8][2];
#pragma unroll
    for (int q = 0; q < 8; q++) { acc[q][0] = 0ull; acc[q][1] = 0ull; }

    for (int cc = 0; cc < 5; cc++) {
        __syncthreads();
        for (int i = tid; i < (CHUNK * HID) / 4; i += 256)
            reinterpret_cast<float4*>(Wc)[i] =
                reinterpret_cast<const float4*>(W1 + cc * CHUNK * HID)[i];
        for (int i = tid; i < 128 * CHUNK; i += 256) {
            int p = i / CHUNK, c = i - p * CHUNK;
            Xs[p * 28 + c] = x[(size_t)(p0 + p) * IDIM + cc * CHUNK + c];
        }
        __syncthreads();

#pragma unroll
        for (int c4 = 0; c4 < 6; c4++) {
#pragma unroll
            for (int half = 0; half < 2; half++) {
                float4 xa[4];
#pragma unroll
                for (int q = 0; q < 4; q++)
                    xa[q] = *reinterpret_cast<const float4*>(
                        &Xs[(ty * 8 + half * 4 + q) * 28 + c4 * 4]);
#pragma unroll
                for (int j = 0; j < 4; j++) {
                    ulonglong2 w = *reinterpret_cast<const ulonglong2*>(
                        &Wc[(c4 * 4 + j) * HID + tx * 4]);
#pragma unroll
                    for (int q = 0; q < 4; q++) {
                        float xv = (j == 0) ? xa[q].x : (j == 1) ? xa[q].y
                                 : (j == 2) ? xa[q].z : xa[q].w;
                        unsigned long long av = pack_dup(xv);
                        fma2(acc[half * 4 + q][0], av, w.x);
                        fma2(acc[half * 4 + q][1], av, w.y);
                    }
                }
            }
        }
        {
            ulonglong2 w = *reinterpret_cast<const ulonglong2*>(&Wc[24 * HID + tx * 4]);
#pragma unroll
            for (int q = 0; q < 8; q++) {
                unsigned long long av = pack_dup(Xs[(ty * 8 + q) * 28 + 24]);
                fma2(acc[q][0], av, w.x);
                fma2(acc[q][1], av, w.y);
            }
        }
    }

    __syncthreads();
    float* hsm = pool;                      // [128][65]
#pragma unroll
    for (int q = 0; q < 8; q++) {
        int p = ty * 8 + q;
        hsm[p * 65 + tx * 4 + 0] = fmaxf(lo32(acc[q][0]) + b1s[tx * 4 + 0], 0.f);
        hsm[p * 65 + tx * 4 + 1] = fmaxf(hi32(acc[q][0]) + b1s[tx * 4 + 1], 0.f);
        hsm[p * 65 + tx * 4 + 2] = fmaxf(lo32(acc[q][1]) + b1s[tx * 4 + 2], 0.f);
        hsm[p * 65 + tx * 4 + 3] = fmaxf(hi32(acc[q][1]) + b1s[tx * 4 + 3], 0.f);
    }
    __syncthreads();

    if (tid < 128) {
        float score = 0.f;
        const float* hp = &hsm[tid * 65];
#pragma unroll
        for (int j = 0; j < HID; j++) score = __fmaf_rn(hp[j], W2s[j], score);
        score += b2[0];
        g_sal[p0 + tid] = 1.f / (1.f + expf(-score));
    }
}

// ---------------------------------------------------------------------------
// K2: cumsum (shfl) + softmax with bit-exact tree reductions + radix-select
// with 8-copy histograms + ranking sort (unchanged from R14, passing)
// ---------------------------------------------------------------------------
__global__ __launch_bounds__(1024)
void batch_kernel(float* __restrict__ ystar_out)
{
    __shared__ unsigned kv[Nq];
    __shared__ float    tsum[1024];
    __shared__ float    fred[32];
    __shared__ unsigned ured[32];
    __shared__ unsigned hC[8 * 256];
    __shared__ unsigned hA[256], hB[256];
    __shared__ unsigned selv[KEFF];
    __shared__ int      seli[KEFF];
    __shared__ int      ranks[KEFF];
    __shared__ float    sh_red;
    __shared__ unsigned sh_prefix, sh_krem, sh_gt;

    const int b = blockIdx.x, t = threadIdx.x;
    const int lane = t & 31, wid = t >> 5;

    float4 sl = *reinterpret_cast<const float4*>(&g_sal[(size_t)b * Nq + 4 * t]);
    float s0 = sl.x, s1 = sl.y, s2 = sl.z, s3 = sl.w;

    float l0 = s0, l1 = l0 + s1, l2 = l1 + s2, l3 = l2 + s3;
    float inc = l3;
#pragma unroll
    for (int off = 1; off < 32; off <<= 1) {
        float v = __shfl_up_sync(0xffffffffu, inc, off);
        if (lane >= off) inc += v;
    }
    if (lane == 31) fred[wid] = inc;
    __syncthreads();
    if (wid == 0) {
        float v = fred[lane], sc = v;
#pragma unroll
        for (int off = 1; off < 32; off <<= 1) {
            float u = __shfl_up_sync(0xffffffffu, sc, off);
            if (lane >= off) sc += u;
        }
        fred[lane] = sc - v;
    }
    __syncthreads();
    {
        float pre = fred[wid] + (inc - l3);
        const float invN = 1.f / (float)Nq;
        float4 c4;
        c4.x = (pre + l0) * invN; c4.y = (pre + l1) * invN;
        c4.z = (pre + l2) * invN; c4.w = (pre + l3) * invN;
        *reinterpret_cast<float4*>(&g_csal[(size_t)b * Nq + 4 * t]) = c4;
    }

    tsum[t] = fmaxf(fmaxf(s0, s1), fmaxf(s2, s3));
    __syncthreads();
#pragma unroll
    for (int off = 512; off >= 32; off >>= 1) {
        if (t < off) tsum[t] = fmaxf(tsum[t], tsum[t + off]);
        __syncthreads();
    }
    if (t < 32) {
        float v = tsum[t];
#pragma unroll
        for (int off = 16; off > 0; off >>= 1)
            v = fmaxf(v, __shfl_down_sync(0xffffffffu, v, off));
        if (t == 0) sh_red = v;
    }
    __syncthreads();
    const float mz = sh_red * 2.0f;
    float e0 = expf(s0 * 2.0f - mz);
    float e1 = expf(s1 * 2.0f - mz);
    float e2 = expf(s2 * 2.0f - mz);
    float e3 = expf(s3 * 2.0f - mz);
    __syncthreads();
    tsum[t] = (e0 + e1) + (e2 + e3);
    __syncthreads();
#pragma unroll
    for (int off = 512; off >= 32; off >>= 1) {
        if (t < off) tsum[t] = tsum[t] + tsum[t + off];
        __syncthreads();
    }
    if (t < 32) {
        float v = tsum[t];
#pragma unroll
        for (int off = 16; off > 0; off >>= 1)
            v = v + __shfl_down_sync(0xffffffffu, v, off);
        if (t == 0) sh_red = v;
    }
    if (t == 0) { sh_prefix = 0u; sh_krem = KEFF; }
    __syncthreads();
    const float S = sh_red;

    float y0 = e0 / S, y1 = e1 / S, y2 = e2 / S, y3 = e3 / S;
    {
        float4 y4; y4.x = y0; y4.y = y1; y4.z = y2; y4.w = y3;
        *reinterpret_cast<float4*>(&ystar_out[(size_t)b * Nq + 4 * t]) = y4;
    }
    kv[4 * t + 0] = __float_as_uint(y0);
    kv[4 * t + 1] = __float_as_uint(y1);
    kv[4 * t + 2] = __float_as_uint(y2);
    kv[4 * t + 3] = __float_as_uint(y3);
    __syncthreads();

#pragma unroll
    for (int round = 0; round < 4; round++) {
        const int shift = 24 - 8 * round;
        const unsigned pmask = (round == 0) ? 0u : (0xFFFFFFFFu << (32 - 8 * round));
        const unsigned pfx  = sh_prefix;
        const unsigned krem = sh_krem;
        hC[t] = 0u; hC[t + 1024] = 0u;
        __syncthreads();
        unsigned* myh = &hC[(t >> 7) << 8];
#pragma unroll
        for (int e = 0; e < 4; e++) {
            unsigned v = kv[4 * t + e];
            if ((v & pmask) == pfx) atomicAdd(&myh[(v >> shift) & 255], 1u);
        }
        __syncthreads();
        if (t < 256) {
            unsigned s = 0;
#pragma unroll
            for (int c = 0; c < 8; c++) s += hC[c * 256 + t];
            hA[t] = s;
        }
        __syncthreads();
        if (wid == 0) {
            unsigned loc[8], tot = 0;
#pragma unroll
            for (int j = 0; j < 8; j++) { loc[j] = hA[lane * 8 + j]; tot += loc[j]; }
            unsigned suf = tot;
#pragma unroll
            for (int off = 1; off < 32; off <<= 1) {
                unsigned v = __shfl_down_sync(0xffffffffu, suf, off);
                if (lane + off < 32) suf += v;
            }
            unsigned run = suf - tot;
#pragma unroll
            for (int j = 7; j >= 0; j--) { run += loc[j]; hB[lane * 8 + j] = run; }
        }
        __syncthreads();
        if (t < 256) {
            unsigned Sb = hB[t];
            unsigned Sn = (t == 255) ? 0u : hB[t + 1];
            if (Sb >= krem && Sn < krem) {
                sh_prefix = pfx | ((unsigned)t << shift);
                sh_krem   = krem - Sn;
            }
        }
        __syncthreads();
    }
    const unsigned T = sh_prefix;
    const unsigned need_eq = sh_krem;

    {
        unsigned c = 0;
#pragma unroll
        for (int e = 0; e < 4; e++) c += (kv[4 * t + e] > T);
        unsigned incu = c;
#pragma unroll
        for (int off = 1; off < 32; off <<= 1) {
            unsigned v = __shfl_up_sync(0xffffffffu, incu, off);
            if (lane >= off) incu += v;
        }
        if (lane == 31) ured[wid] = incu;
        __syncthreads();
        if (wid == 0) {
            unsigned v = ured[lane], sc = v;
#pragma unroll
            for (int off = 1; off < 32; off <<= 1) {
                unsigned u = __shfl_up_sync(0xffffffffu, sc, off);
                if (lane >= off) sc += u;
            }
            ured[lane] = sc - v;
        }
        __syncthreads();
        unsigned pos = ured[wid] + incu - c;
        if (t == 1023) sh_gt = pos + c;
#pragma unroll
        for (int e = 0; e < 4; e++) {
            int i = 4 * t + e;
            unsigned v = kv[i];
            if (v > T) { selv[pos] = v; seli[pos] = i; pos++; }
        }
        __syncthreads();
    }
    {
        const unsigned gt = sh_gt;
        unsigned c = 0;
#pragma unroll
        for (int e = 0; e < 4; e++) c += (kv[4 * t + e] == T);
        unsigned incu = c;
#pragma unroll
        for (int off = 1; off < 32; off <<= 1) {
            unsigned v = __shfl_up_sync(0xffffffffu, incu, off);
            if (lane >= off) incu += v;
        }
        if (lane == 31) ured[wid] = incu;
        __syncthreads();
        if (wid == 0) {
            unsigned v = ured[lane], sc = v;
#pragma unroll
            for (int off = 1; off < 32; off <<= 1) {
                unsigned u = __shfl_up_sync(0xffffffffu, sc, off);
                if (lane >= off) sc += u;
            }
            ured[lane] = sc - v;
        }
        __syncthreads();
        unsigned pos = ured[wid] + incu - c;
#pragma unroll
        for (int e = 0; e < 4; e++) {
            int i = 4 * t + e;
            if (kv[i] == T) {
                if (pos < need_eq) { selv[gt + pos] = T; seli[gt + pos] = i; }
                pos++;
            }
        }
        __syncthreads();
    }

    if (t < 256) ranks[t] = 0;
    __syncthreads();
    {
        const int i = t & 255, part = t >> 8;
        const unsigned vi = selv[i];
        const int ii = seli[i];
        int cnt = 0;
#pragma unroll 8
        for (int j = part * 64; j < part * 64 + 64; j++) {
            unsigned vj = selv[j];
            int ij = seli[j];
            cnt += (vj > vi) || (vj == vi && ij < ii);
        }
        if (cnt) atomicAdd(&ranks[i], cnt);
    }
    __syncthreads();
    if (t < 256) g_top[b * KEFF + ranks[t]] = seli[t];
}

// ---------------------------------------------------------------------------
// K3: warp-per-point gather + normalize + lift (unchanged)
// ---------------------------------------------------------------------------
__global__ __launch_bounds__(256)
void lift_kernel(const float* __restrict__ x,
                 const float* __restrict__ liftW, const float* __restrict__ liftb,
                 const float* __restrict__ mu,    const float* __restrict__ sigma)
{
    __shared__ float Ws[ADIM * KDIM];
    __shared__ float mus[ADIM], rs[ADIM], lbs[KDIM];
    __shared__ float wsh[8][ADIM];

    const int tid = threadIdx.x;
    for (int i = tid; i < (ADIM * KDIM) / 4; i += 256)
        reinterpret_cast<float4*>(Ws)[i] = reinterpret_cast<const float4*>(liftW)[i];
    if (tid < ADIM) { mus[tid] = mu[tid]; rs[tid] = 1.f / sigma[tid]; }
    if (tid < KDIM) lbs[tid] = liftb[tid];

    const int w = tid >> 5, l = tid & 31;
    const int b     = blockIdx.x >> 2;
    const int kbase = (blockIdx.x & 3) * 64;
    __syncthreads();

    for (int it = 0; it < 8; it++) {
        const int k   = kbase + it * 8 + w;
        const int idx = g_top[b * KEFF + k];
        const float* xr = x + ((size_t)b * Nq + idx) * IDIM;

        float v[4];
#pragma unroll
        for (int q = 0; q < 4; q++) {
            int a = q * 32 + l;
            float val;
            if (a < IDIM)       val = xr[a];
            else if (a == 125)  val = g_sal [(size_t)b * Nq + idx];
            else if (a == 126)  val = (float)idx * (1.f / (float)(Nq - 1));
            else                val = g_csal[(size_t)b * Nq + idx];
            v[q] = val;
        }
        float ss = (v[0] * v[0] + v[1] * v[1]) + (v[2] * v[2] + v[3] * v[3]);
#pragma unroll
        for (int o = 16; o > 0; o >>= 1) ss += __shfl_xor_sync(0xffffffffu, ss, o);
        const float sc = 1.f / (sqrtf(ss) + EPSq);
#pragma unroll
        for (int q = 0; q < 4; q++) {
            int a = q * 32 + l;
            wsh[w][a] = (v[q] * sc - mus[a]) * rs[a];
        }
        __syncwarp();

        unsigned long long acc = pack2(lbs[2 * l], lbs[2 * l + 1]);
#pragma unroll 8
        for (int a = 0; a < ADIM; a++) {
            unsigned long long wpair =
                *reinterpret_cast<const unsigned long long*>(&Ws[a * KDIM + 2 * l]);
            fma2(acc, pack_dup(wsh[w][a]), wpair);
        }
        float2 o; o.x = lo32(acc); o.y = hi32(acc);
        *reinterpret_cast<float2*>(&g_cloud[((size_t)b * KEFF + k) * KDIM + 2 * l]) = o;
        __syncwarp();
    }
}

// ---------------------------------------------------------------------------
// K4: tokens via fp16 mma.sync.m16n8k16 + ldmatrix fragments.
// CTA = 128 rows x 64 cols, 256 threads; warp = 16 rows x 64 cols
// = 8 m16n8 tiles x 4 k-steps.
// Ah[128][64] halves (128B rows, Swizzle<3,4,3>: byte ^ ((row&7)<<4)), 16 KB
// Bh[64][64]  halves (same swizzle), 8 KB. Total 24 KB static smem.
// Per k-step: 1 A-ldmatrix.x4 + 4 B-ldmatrix.x4 + 8 MMA.
// ---------------------------------------------------------------------------
struct __align__(128) TkSmem {
    uint32_t A[128 * 32];   // 128 rows x 64 halves
    uint32_t B[64 * 32];    // 64 rows x 64 halves
};

__global__ __launch_bounds__(256, 4)
void tokens_mma_kernel(const float* __restrict__ projW, const float* __restrict__ projb,
                       float* __restrict__ out)
{
    __shared__ TkSmem sms;
    char* Ab = reinterpret_cast<char*>(sms.A);
    char* Bb = reinterpret_cast<char*>(sms.B);

    const int tid = threadIdx.x;
    const int warp = tid >> 5, lane = tid & 31;
    const int qid = lane >> 2, qtd = lane & 3;
    const int r0 = blockIdx.y * 128;
    const int d0 = blockIdx.x * 64;

    // ---- stage A: cloud rows fp32 -> half, swizzled rows ----
    for (int i = tid; i < 2048; i += 256) {
        int r = i >> 4, c4 = i & 15;
        float4 v = *reinterpret_cast<const float4*>(
            &g_cloud[(size_t)(r0 + r) * KDIM + c4 * 4]);
        uint32_t byte = (uint32_t)(r * 128 + c4 * 8);
        uint32_t swz = byte ^ ((uint32_t)(r & 7) << 4);
        uint2 w; w.x = h2pack(v.x, v.y); w.y = h2pack(v.z, v.w);
        *reinterpret_cast<uint2*>(Ab + swz) = w;
    }
    // ---- stage B: projW[k][d0+n] -> Bh[n][k] halves (transpose), swizzled ----
    for (int i = tid; i < 512; i += 256) {
        int pr = i >> 4, n4 = i & 15;                    // k-pair, float4 col group
        const float4 ve = *reinterpret_cast<const float4*>(
            &projW[(size_t)(2 * pr) * DMOD + d0 + n4 * 4]);
        const float4 vo = *reinterpret_cast<const float4*>(
            &projW[(size_t)(2 * pr + 1) * DMOD + d0 + n4 * 4]);
        float e[4] = { ve.x, ve.y, ve.z, ve.w };
        float o[4] = { vo.x, vo.y, vo.z, vo.w };
#pragma unroll
        for (int q = 0; q < 4; q++) {
            int n = n4 * 4 + q;
            uint32_t byte = (uint32_t)(n * 128 + pr * 4);
            uint32_t swz = byte ^ ((uint32_t)(n & 7) << 4);
            *reinterpret_cast<uint32_t*>(Bb + swz) = h2pack(e[q], o[q]);
        }
    }
    __syncthreads();

    // ---- fragment addresses ----
    const uint32_t a_s = smem_u32(sms.A);
    const uint32_t b_s = smem_u32(sms.B);
    const int rowA = warp * 16 + (lane & 15);
    const uint32_t a_raw = a_s + (uint32_t)(rowA * 128 + ((lane >> 4) << 4));
    const uint32_t a_x = (uint32_t)(rowA & 7) << 4;
    const int nb = ((lane >> 4) << 3) + (lane & 7);      // n within nt-pair: 0..15
    const uint32_t b_raw = b_s + (uint32_t)(nb * 128 + (((lane >> 3) & 1) << 4));
    const uint32_t b_x = (uint32_t)(lane & 7) << 4;

    float c[8][4];
#pragma unroll
    for (int nt = 0; nt < 8; nt++)
#pragma unroll
        for (int j = 0; j < 4; j++) c[nt][j] = 0.f;

#pragma unroll
    for (int ks = 0; ks < 4; ks++) {
        uint32_t a0, a1, a2, a3;
        ldsm_x4(a0, a1, a2, a3, (a_raw + ks * 32) ^ a_x);
#pragma unroll
        for (int p = 0; p < 4; p++) {                    // nt0 = 2p
            uint32_t b0, b1, b2, b3;
            ldsm_x4(b0, b1, b2, b3, (b_raw + (uint32_t)(p * 2048 + ks * 32)) ^ b_x);
            asm volatile(
                "mma.sync.aligned.m16n8k16.row.col.f32.f16.f16.f32 "
                "{%0,%1,%2,%3}, {%4,%5,%6,%7}, {%8,%9}, {%0,%1,%2,%3};"
                : "+f"(c[2*p][0]), "+f"(c[2*p][1]), "+f"(c[2*p][2]), "+f"(c[2*p][3])
                : "r"(a0), "r"(a1), "r"(a2), "r"(a3), "r"(b0), "r"(b1));
            asm volatile(
                "mma.sync.aligned.m16n8k16.row.col.f32.f16.f16.f32 "
                "{%0,%1,%2,%3}, {%4,%5,%6,%7}, {%8,%9}, {%0,%1,%2,%3};"
                : "+f"(c[2*p+1][0]), "+f"(c[2*p+1][1]), "+f"(c[2*p+1][2]), "+f"(c[2*p+1][3])
                : "r"(a0), "r"(a1), "r"(a2), "r"(a3), "r"(b2), "r"(b3));
        }
    }

    // ---- epilogue: c0,c1 -> (row, col..col+1); c2,c3 -> (row+8, ...) ----
    const size_t rowO = (size_t)(r0 + warp * 16 + qid);
#pragma unroll
    for (int nt = 0; nt < 8; nt++) {
        const int col = d0 + nt * 8 + qtd * 2;
        const float pb0 = projb[col], pb1 = projb[col + 1];
        float2 o1, o2;
        o1.x = c[nt][0] + pb0; o1.y = c[nt][1] + pb1;
        o2.x = c[nt][2] + pb0; o2.y = c[nt][3] + pb1;
        *reinterpret_cast<float2*>(&out[rowO * DMOD + col]) = o1;
        *reinterpret_cast<float2*>(&out[(rowO + 8) * DMOD + col]) = o2;
    }
}

// ---------------------------------------------------------------------------
extern "C" void kernel_launch(void* const* d_in, const int* in_sizes, int n_in,
                              void* d_out, int out_size)
{
    const float* x     = (const float*)d_in[0];
    const float* W1    = (const float*)d_in[1];
    const float* b1    = (const float*)d_in[2];
    const float* W2    = (const float*)d_in[3];
    const float* b2    = (const float*)d_in[4];
    const float* liftW = (const float*)d_in[5];
    const float* liftb = (const float*)d_in[6];
    const float* mu    = (const float*)d_in[7];
    const float* sigma = (const float*)d_in[8];
    const float* projW = (const float*)d_in[9];
    const float* projb = (const float*)d_in[10];

    float* out    = (float*)d_out;
    float* tokens = out;                                   // [32,256,1024]
    float* ystar  = out + (size_t)Bq * KEFF * DMOD;        // [32,4096]

    mlp_kernel  <<<(Bq * Nq) / 128, 256>>>(x, W1, b1, W2, b2);
    batch_kernel<<<Bq, 1024>>>(ystar);
    lift_kernel <<<Bq * 4, 256>>>(x, liftW, liftb, mu, sigma);
    tokens_mma_kernel<<<dim3(DMOD / 64, (Bq * KEFF) / 128), 256>>>(
        projW, projb, tokens);
}